// round 15
// baseline (speedup 1.0000x reference)
#include <cuda_runtime.h>
#include <cuda_fp16.h>

#define HID    128
#define INPUT  24
#define SLOTS  16
#define TSTEPS 128
#define BATCH  2048
#define NKA    18      // fused GEMM_A ksteps: 10 layer0 (128h+24x+8pad) + 8 Whh1
#define NKB    8       // GEMM_B ksteps: Wih1 (128)

// ---------------- packed fp16 weight fragments (device globals; no allocation) ----------------
// B-fragment order for mma.m16n8k16.row.col:
//   idx = (((ks*16 + w)*2 + q)*32 + l)*4 + r ;  g = q*2 + (r>>1), p = r&1
//   word = half2( W[n][k0], W[n][k0+1] ),  n = g*128 + w*8 + (l>>2),  k0 = ks*16 + (l&3)*2 + 8*p
__device__ unsigned g_PA[NKA * 4096];   // 288 KB: ks<10 layer0, ks>=10 Whh1
__device__ unsigned g_PB[NKB * 4096];   // 128 KB: Wih1
__device__ float g_B0[512];             // bih0 + bhh0, gate-major n index
__device__ float g_B1[512];

__global__ void prep_kernel(const float* __restrict__ Wih0, const float* __restrict__ Whh0,
                            const float* __restrict__ bih0, const float* __restrict__ bhh0,
                            const float* __restrict__ Wih1, const float* __restrict__ Whh1,
                            const float* __restrict__ bih1, const float* __restrict__ bhh1) {
    int idx = blockIdx.x * blockDim.x + threadIdx.x;
    const int NPA = NKA * 4096;
    const int NPB = NKB * 4096;
    if (idx < NPA) {
        int r = idx & 3, l = (idx >> 2) & 31, q = (idx >> 7) & 1, w = (idx >> 8) & 15, ks = idx >> 12;
        int g = q * 2 + (r >> 1), p = r & 1;
        int n = g * 128 + w * 8 + (l >> 2);
        float v0, v1;
        if (ks < 10) {
            int k0 = ks * 16 + (l & 3) * 2 + 8 * p;
            int k1 = k0 + 1;
            v0 = (k0 < HID) ? Whh0[n * HID + k0]
                            : ((k0 < HID + INPUT) ? Wih0[n * INPUT + (k0 - HID)] : 0.f);
            v1 = (k1 < HID) ? Whh0[n * HID + k1]
                            : ((k1 < HID + INPUT) ? Wih0[n * INPUT + (k1 - HID)] : 0.f);
        } else {
            int k0 = (ks - 10) * 16 + (l & 3) * 2 + 8 * p;
            v0 = Whh1[n * HID + k0];
            v1 = Whh1[n * HID + k0 + 1];
        }
        __half2 hv = __halves2half2(__float2half_rn(v0), __float2half_rn(v1));
        g_PA[idx] = *(unsigned*)&hv;
        return;
    }
    idx -= NPA;
    if (idx < NPB) {
        int r = idx & 3, l = (idx >> 2) & 31, q = (idx >> 7) & 1, w = (idx >> 8) & 15, ks = idx >> 12;
        int g = q * 2 + (r >> 1), p = r & 1;
        int n = g * 128 + w * 8 + (l >> 2);
        int k0 = ks * 16 + (l & 3) * 2 + 8 * p;
        __half2 hv = __halves2half2(__float2half_rn(Wih1[n * HID + k0]),
                                    __float2half_rn(Wih1[n * HID + k0 + 1]));
        g_PB[idx] = *(unsigned*)&hv;
        return;
    }
    idx -= NPB;
    if (idx < 1024) {
        int n = idx & 511;
        if (idx < 512) g_B0[n] = bih0[n] + bhh0[n];
        else           g_B1[n] = bih1[n] + bhh1[n];
    }
}

// ---------------- math helpers ----------------
__device__ __forceinline__ float sigf(float v) {
    return __fdividef(1.f, 1.f + __expf(-v));
}
__device__ __forceinline__ float tanhf_fast(float v) {
    return __fdividef(2.f, 1.f + __expf(-2.f * v)) - 1.f;
}

__device__ __forceinline__ void mma_f16(float d[4], const unsigned a[4], unsigned b0, unsigned b1) {
    asm volatile(
        "mma.sync.aligned.m16n8k16.row.col.f32.f16.f16.f32 "
        "{%0,%1,%2,%3}, {%4,%5,%6,%7}, {%8,%9}, {%0,%1,%2,%3};"
        : "+f"(d[0]), "+f"(d[1]), "+f"(d[2]), "+f"(d[3])
        : "r"(a[0]), "r"(a[1]), "r"(a[2]), "r"(a[3]), "r"(b0), "r"(b1));
}

// ---- smem word-offset layout (unsigned units) ----
#define H1O0  0         // h1 ping  (8 ksteps)
#define H1O1  1024      // h1 pong
#define XO0   2048      // x ping   (2 ksteps)
#define XO1   2304      // x pong
#define H2O   2560      // h2       (8 ksteps)
#define AAW   3584      // 14.3 KB

// Fused GEMM_A: 18 ksteps; ks<10 -> d0, ks>=10 -> d1. Persistent B ring b[4][2]:
// slot (ks+OFF)&3; each kstep refills its slot with kstep ks+4 (crossing into PB
// for ks>=14 -> GEMM_B never cold-starts).
template <int OFF>
__device__ __forceinline__ void gemm_A(const uint4* __restrict__ PAb, const uint4* __restrict__ PBb,
                                       const unsigned* __restrict__ h1c,
                                       const unsigned* __restrict__ xc,
                                       const unsigned* __restrict__ h2b,
                                       int l, float d0[4][4], float d1[4][4], uint4 b[4][2]) {
    unsigned a[2][4];
    *(uint4*)a[0] = *(const uint4*)(h1c + l * 4);
#pragma unroll
    for (int ks = 0; ks < NKA; ks++) {
        if (ks + 1 < NKA) {
            const unsigned* nb = (ks + 1 < 8) ? h1c + (ks + 1) * 128
                               : (ks + 1 < 10) ? xc + (ks + 1 - 8) * 128
                                               : h2b + (ks + 1 - 10) * 128;
            *(uint4*)a[(ks + 1) & 1] = *(const uint4*)(nb + l * 4);
        }
        const unsigned* ac = a[ks & 1];
        float(*d)[4] = (ks < 10) ? d0 : d1;
        const int slot = (ks + OFF) & 3;
        mma_f16(d[0], ac, b[slot][0].x, b[slot][0].y);
        mma_f16(d[1], ac, b[slot][0].z, b[slot][0].w);
        mma_f16(d[2], ac, b[slot][1].x, b[slot][1].y);
        mma_f16(d[3], ac, b[slot][1].z, b[slot][1].w);
        const uint4* src = (ks + 4 < NKA) ? PAb + (ks + 4) * 1024 : PBb + (ks + 4 - NKA) * 1024;
        b[slot][0] = src[0];
        b[slot][1] = src[32];
    }
}

// GEMM_B: 8 ksteps of Wih1 x h1(t) into d1; refills cross into PA (next step's ks0-3).
template <int OFF>
__device__ __forceinline__ void gemm_B(const uint4* __restrict__ PBb, const uint4* __restrict__ PAb,
                                       const unsigned* __restrict__ h1n,
                                       int l, float d1[4][4], uint4 b[4][2]) {
    unsigned a[2][4];
    *(uint4*)a[0] = *(const uint4*)(h1n + l * 4);
#pragma unroll
    for (int ks = 0; ks < NKB; ks++) {
        if (ks + 1 < NKB)
            *(uint4*)a[(ks + 1) & 1] = *(const uint4*)(h1n + (ks + 1) * 128 + l * 4);
        const unsigned* ac = a[ks & 1];
        const int slot = (ks + OFF) & 3;
        mma_f16(d1[0], ac, b[slot][0].x, b[slot][0].y);
        mma_f16(d1[1], ac, b[slot][0].z, b[slot][0].w);
        mma_f16(d1[2], ac, b[slot][1].x, b[slot][1].y);
        mma_f16(d1[3], ac, b[slot][1].z, b[slot][1].w);
        const uint4* src = (ks + 4 < NKB) ? PBb + (ks + 4) * 1024 : PAb + (ks - 4) * 1024;
        b[slot][0] = src[0];
        b[slot][1] = src[32];
    }
}

// cell update for this lane's 4 cells; returns two packed half2 words (rows r0, r0+8).
__device__ __forceinline__ void cell4(const float d[4][4], float c[4],
                                      unsigned& hlo, unsigned& hhi) {
    float h[4];
#pragma unroll
    for (int i = 0; i < 4; i++) {
        float iv = sigf(d[0][i]);
        float fv = sigf(d[1][i]);
        float gv = tanhf_fast(d[2][i]);
        float ov = sigf(d[3][i]);
        c[i] = fv * c[i] + iv * gv;
        h[i] = ov * tanhf_fast(c[i]);
    }
    __half2 a = __halves2half2(__float2half_rn(h[0]), __float2half_rn(h[1]));
    __half2 b = __halves2half2(__float2half_rn(h[2]), __float2half_rn(h[3]));
    hlo = *(unsigned*)&a;
    hhi = *(unsigned*)&b;
}

// half index (within one kstep) for A-frag value (row r, col jl in 0..15)
__device__ __forceinline__ int ahalf_idx(int r, int jl) {
    int lanep = (r & 7) * 4 + ((jl & 7) >> 1);
    int e = ((r >> 3) & 1) + 2 * ((jl >> 3) & 1);
    return (lanep * 4 + e) * 2 + (jl & 1);
}

__global__ __launch_bounds__(512, 1) void lstm_kernel(const float* __restrict__ x,
                                                      const float* __restrict__ Wfc,
                                                      const float* __restrict__ bfc,
                                                      float* __restrict__ out) {
    __shared__ __align__(16) unsigned AA[AAW];

    const int tid = threadIdx.x;
    const int w = tid >> 5;
    const int l = tid & 31;
    const int b0 = blockIdx.x * SLOTS;

    for (int i = tid; i < AAW; i += 512) AA[i] = 0u;
    __syncthreads();  // zeros visible before x(0) half-stores

    // stage x(0) into X ping
    if (tid < INPUT * SLOTS) {
        int s = tid & 15, k = tid >> 4;
        float v = x[(size_t)(b0 + s) * (TSTEPS * INPUT) + k];
        ((__half*)(AA + XO0))[(k >> 4) * 256 + ahalf_idx(s, k & 15)] = __float2half_rn(v);
    }

    // bias preload
    const int j0 = w * 8 + (l & 3) * 2;
    float bi0[4][2], bi1[4][2];
#pragma unroll
    for (int g = 0; g < 4; g++) {
        bi0[g][0] = g_B0[g * 128 + j0];
        bi0[g][1] = g_B0[g * 128 + j0 + 1];
        bi1[g][0] = g_B1[g * 128 + j0];
        bi1[g][1] = g_B1[g * 128 + j0 + 1];
    }

    float c0[4] = {0.f, 0.f, 0.f, 0.f};
    float c1[4] = {0.f, 0.f, 0.f, 0.f};

    const uint4* PAb = (const uint4*)g_PA + w * 64 + l;
    const uint4* PBb = (const uint4*)g_PB + w * 64 + l;
    __syncthreads();

    const int wbase = (w >> 1) * 128 + l * 4 + 2 * (w & 1);
    const int xs = tid & 15, xk = tid >> 4;  // x-staging coords (valid when tid<384)

    // B-ring prologue: PA ks0..3 -> slots 0..3
    uint4 b[4][2];
#pragma unroll
    for (int p = 0; p < 4; p++) {
        b[p][0] = PAb[p * 1024];
        b[p][1] = PAb[p * 1024 + 32];
    }

#pragma unroll 1
    for (int t2 = 0; t2 < TSTEPS; t2 += 2) {
#pragma unroll
        for (int half = 0; half < 2; half++) {
            const int t = t2 + half;
            const int h1c = half ? H1O1 : H1O0;    // current h1/x buffers
            const int h1n = half ? H1O0 : H1O1;    // next (written this step)
            const int xc = half ? XO1 : XO0;
            const int xn = half ? XO0 : XO1;

            // prefetch x(t+1) into registers (off the barrier path)
            float xv = 0.f;
            if (tid < INPUT * SLOTS) {
                int tn = (t + 1 < TSTEPS) ? t + 1 : t;
                xv = x[(size_t)(b0 + xs) * (TSTEPS * INPUT) + tn * INPUT + xk];
            }

            float d0[4][4], d1[4][4];
#pragma unroll
            for (int g = 0; g < 4; g++) {
                d0[g][0] = bi0[g][0]; d0[g][1] = bi0[g][1];
                d0[g][2] = bi0[g][0]; d0[g][3] = bi0[g][1];
                d1[g][0] = bi1[g][0]; d1[g][1] = bi1[g][1];
                d1[g][2] = bi1[g][0]; d1[g][3] = bi1[g][1];
            }

            // ---- fused GEMM_A (reads h1 ping/x ping/h2; B-ring stays full) ----
            if (half == 0) gemm_A<0>(PAb, PBb, AA + h1c, AA + xc, AA + H2O, l, d0, d1, b);
            else           gemm_A<2>(PAb, PBb, AA + h1c, AA + xc, AA + H2O, l, d0, d1, b);

            // ---- epi0: writes go to PONG regions (no barrier needed before) ----
            {
                unsigned hlo, hhi;
                cell4(d0, c0, hlo, hhi);
                AA[h1n + wbase] = hlo;
                AA[h1n + wbase + 1] = hhi;
            }
            if (tid < INPUT * SLOTS)
                ((__half*)(AA + xn))[(xk >> 4) * 256 + ahalf_idx(xs, xk & 15)] = __float2half_rn(xv);
            __syncthreads();  // publish h1(t) + x(t+1)

            // ---- GEMM_B (reads new h1; refills PA for t+1) + epi1 ----
            if (half == 0) gemm_B<2>(PBb, PAb, AA + h1n, l, d1, b);
            else           gemm_B<0>(PBb, PAb, AA + h1n, l, d1, b);
            {
                unsigned hlo, hhi;
                cell4(d1, c1, hlo, hhi);
                AA[H2O + wbase] = hlo;
                AA[H2O + wbase + 1] = hhi;
            }
            __syncthreads();  // publish h2(t)
        }
    }

    // ---- final FC: out[b] = h2_last[b] . Wfc + bfc  (warp w -> batch row w) ----
    {
        int r = w;
        float s = 0.f;
#pragma unroll
        for (int jj = 0; jj < 4; jj++) {
            int j = l + jj * 32;
            float hv = __half2float(((__half*)(AA + H2O))[(j >> 4) * 256 + ahalf_idx(r, j & 15)]);
            s += hv * Wfc[j];
        }
#pragma unroll
        for (int o = 16; o > 0; o >>= 1) s += __shfl_down_sync(0xffffffffu, s, o);
        if (l == 0) out[b0 + r] = s + bfc[0];
    }
}

extern "C" void kernel_launch(void* const* d_in, const int* in_sizes, int n_in,
                              void* d_out, int out_size) {
    const float* x    = (const float*)d_in[0];
    const float* Wih0 = (const float*)d_in[1];
    const float* Whh0 = (const float*)d_in[2];
    const float* bih0 = (const float*)d_in[3];
    const float* bhh0 = (const float*)d_in[4];
    const float* Wih1 = (const float*)d_in[5];
    const float* Whh1 = (const float*)d_in[6];
    const float* bih1 = (const float*)d_in[7];
    const float* bhh1 = (const float*)d_in[8];
    const float* Wfc  = (const float*)d_in[9];
    const float* bfc  = (const float*)d_in[10];
    float* out = (float*)d_out;

    const int prep_total = NKA * 4096 + NKB * 4096 + 1024;
    prep_kernel<<<(prep_total + 255) / 256, 256>>>(Wih0, Whh0, bih0, bhh0, Wih1, Whh1, bih1, bhh1);
    lstm_kernel<<<BATCH / SLOTS, 512>>>(x, Wfc, bfc, out);
}

// round 16
// speedup vs baseline: 1.4114x; 1.4114x over previous
#include <cuda_runtime.h>
#include <cuda_fp16.h>

#define HID    128
#define INPUT  24
#define SLOTS  16
#define TSTEPS 128
#define BATCH  2048
#define NKA    18      // fused GEMM_A ksteps: 10 layer0 (128h+24x+8pad) + 8 Whh1
#define NKB    8       // GEMM_B ksteps: Wih1 (128)

// ---------------- packed fp16 weight fragments (device globals; no allocation) ----------------
// B-fragment order for mma.m16n8k16.row.col:
//   idx = (((ks*16 + w)*2 + q)*32 + l)*4 + r ;  g = q*2 + (r>>1), p = r&1
//   word = half2( W[n][k0], W[n][k0+1] ),  n = g*128 + w*8 + (l>>2),  k0 = ks*16 + (l&3)*2 + 8*p
__device__ unsigned g_PA[NKA * 4096];   // 288 KB: ks<10 layer0, ks>=10 Whh1
__device__ unsigned g_PB[NKB * 4096];   // 128 KB: Wih1
__device__ float g_B0[512];             // bih0 + bhh0, gate-major n index
__device__ float g_B1[512];

__global__ void prep_kernel(const float* __restrict__ Wih0, const float* __restrict__ Whh0,
                            const float* __restrict__ bih0, const float* __restrict__ bhh0,
                            const float* __restrict__ Wih1, const float* __restrict__ Whh1,
                            const float* __restrict__ bih1, const float* __restrict__ bhh1) {
    int idx = blockIdx.x * blockDim.x + threadIdx.x;
    const int NPA = NKA * 4096;
    const int NPB = NKB * 4096;
    if (idx < NPA) {
        int r = idx & 3, l = (idx >> 2) & 31, q = (idx >> 7) & 1, w = (idx >> 8) & 15, ks = idx >> 12;
        int g = q * 2 + (r >> 1), p = r & 1;
        int n = g * 128 + w * 8 + (l >> 2);
        float v0, v1;
        if (ks < 10) {
            int k0 = ks * 16 + (l & 3) * 2 + 8 * p;
            int k1 = k0 + 1;
            v0 = (k0 < HID) ? Whh0[n * HID + k0]
                            : ((k0 < HID + INPUT) ? Wih0[n * INPUT + (k0 - HID)] : 0.f);
            v1 = (k1 < HID) ? Whh0[n * HID + k1]
                            : ((k1 < HID + INPUT) ? Wih0[n * INPUT + (k1 - HID)] : 0.f);
        } else {
            int k0 = (ks - 10) * 16 + (l & 3) * 2 + 8 * p;
            v0 = Whh1[n * HID + k0];
            v1 = Whh1[n * HID + k0 + 1];
        }
        __half2 hv = __halves2half2(__float2half_rn(v0), __float2half_rn(v1));
        g_PA[idx] = *(unsigned*)&hv;
        return;
    }
    idx -= NPA;
    if (idx < NPB) {
        int r = idx & 3, l = (idx >> 2) & 31, q = (idx >> 7) & 1, w = (idx >> 8) & 15, ks = idx >> 12;
        int g = q * 2 + (r >> 1), p = r & 1;
        int n = g * 128 + w * 8 + (l >> 2);
        int k0 = ks * 16 + (l & 3) * 2 + 8 * p;
        __half2 hv = __halves2half2(__float2half_rn(Wih1[n * HID + k0]),
                                    __float2half_rn(Wih1[n * HID + k0 + 1]));
        g_PB[idx] = *(unsigned*)&hv;
        return;
    }
    idx -= NPB;
    if (idx < 1024) {
        int n = idx & 511;
        if (idx < 512) g_B0[n] = bih0[n] + bhh0[n];
        else           g_B1[n] = bih1[n] + bhh1[n];
    }
}

// ---------------- math helpers ----------------
__device__ __forceinline__ float sigf(float v) {
    return __fdividef(1.f, 1.f + __expf(-v));
}
__device__ __forceinline__ float tanhf_fast(float v) {
    return __fdividef(2.f, 1.f + __expf(-2.f * v)) - 1.f;
}

__device__ __forceinline__ void mma_f16(float d[4], const unsigned a[4], unsigned b0, unsigned b1) {
    asm volatile(
        "mma.sync.aligned.m16n8k16.row.col.f32.f16.f16.f32 "
        "{%0,%1,%2,%3}, {%4,%5,%6,%7}, {%8,%9}, {%0,%1,%2,%3};"
        : "+f"(d[0]), "+f"(d[1]), "+f"(d[2]), "+f"(d[3])
        : "r"(a[0]), "r"(a[1]), "r"(a[2]), "r"(a[3]), "r"(b0), "r"(b1));
}

// ---- smem word-offset layout (unsigned units) ----
#define H1O0  0         // h1 ping  (8 ksteps)
#define H1O1  1024      // h1 pong
#define XO0   2048      // x ping   (2 ksteps)
#define XO1   2304      // x pong
#define H2O   2560      // h2       (8 ksteps)
#define AAW   3584      // 14.3 KB

// Fused GEMM_A: 18 ksteps, fully unrolled; ks<10 -> d0, ks>=10 -> d1.
// Local 4-deep circular B prefetch (as R14: ring dies at return -> no spill pressure).
// Region selects (h1/x/h2) are compile-time under the unroll.
__device__ __forceinline__ void gemm_A(const uint4* __restrict__ base,
                                       const unsigned* __restrict__ h1c,
                                       const unsigned* __restrict__ xc,
                                       const unsigned* __restrict__ h2b,
                                       int l, float d0[4][4], float d1[4][4]) {
    uint4 b[4][2];
#pragma unroll
    for (int p = 0; p < 4; p++) {
        b[p][0] = base[p * 1024];
        b[p][1] = base[p * 1024 + 32];
    }
    unsigned a[2][4];
    *(uint4*)a[0] = *(const uint4*)(h1c + l * 4);
#pragma unroll
    for (int ks = 0; ks < NKA; ks++) {
        if (ks + 1 < NKA) {
            const unsigned* nb = (ks + 1 < 8) ? h1c + (ks + 1) * 128
                               : (ks + 1 < 10) ? xc + (ks + 1 - 8) * 128
                                               : h2b + (ks + 1 - 10) * 128;
            *(uint4*)a[(ks + 1) & 1] = *(const uint4*)(nb + l * 4);
        }
        const unsigned* ac = a[ks & 1];
        float(*d)[4] = (ks < 10) ? d0 : d1;
        const int slot = ks & 3;
        mma_f16(d[0], ac, b[slot][0].x, b[slot][0].y);
        mma_f16(d[1], ac, b[slot][0].z, b[slot][0].w);
        mma_f16(d[2], ac, b[slot][1].x, b[slot][1].y);
        mma_f16(d[3], ac, b[slot][1].z, b[slot][1].w);
        if (ks + 4 < NKA) {
            b[slot][0] = base[(ks + 4) * 1024];
            b[slot][1] = base[(ks + 4) * 1024 + 32];
        }
    }
}

// GEMM_B: 8 ksteps of Wih1 x h1(t) into d1 (local B ring).
__device__ __forceinline__ void gemm_B(const uint4* __restrict__ base,
                                       const unsigned* __restrict__ h1n,
                                       int l, float d1[4][4]) {
    uint4 b[4][2];
#pragma unroll
    for (int p = 0; p < 4; p++) {
        b[p][0] = base[p * 1024];
        b[p][1] = base[p * 1024 + 32];
    }
    unsigned a[2][4];
    *(uint4*)a[0] = *(const uint4*)(h1n + l * 4);
#pragma unroll
    for (int ks = 0; ks < NKB; ks++) {
        if (ks + 1 < NKB)
            *(uint4*)a[(ks + 1) & 1] = *(const uint4*)(h1n + (ks + 1) * 128 + l * 4);
        const unsigned* ac = a[ks & 1];
        const int slot = ks & 3;
        mma_f16(d1[0], ac, b[slot][0].x, b[slot][0].y);
        mma_f16(d1[1], ac, b[slot][0].z, b[slot][0].w);
        mma_f16(d1[2], ac, b[slot][1].x, b[slot][1].y);
        mma_f16(d1[3], ac, b[slot][1].z, b[slot][1].w);
        if (ks + 4 < NKB) {
            b[slot][0] = base[(ks + 4) * 1024];
            b[slot][1] = base[(ks + 4) * 1024 + 32];
        }
    }
}

// cell update for this lane's 4 cells; returns two packed half2 words (rows r0, r0+8).
__device__ __forceinline__ void cell4(const float d[4][4], float c[4],
                                      unsigned& hlo, unsigned& hhi) {
    float h[4];
#pragma unroll
    for (int i = 0; i < 4; i++) {
        float iv = sigf(d[0][i]);
        float fv = sigf(d[1][i]);
        float gv = tanhf_fast(d[2][i]);
        float ov = sigf(d[3][i]);
        c[i] = fv * c[i] + iv * gv;
        h[i] = ov * tanhf_fast(c[i]);
    }
    __half2 a = __halves2half2(__float2half_rn(h[0]), __float2half_rn(h[1]));
    __half2 b = __halves2half2(__float2half_rn(h[2]), __float2half_rn(h[3]));
    hlo = *(unsigned*)&a;
    hhi = *(unsigned*)&b;
}

// half index (within one kstep) for A-frag value (row r, col jl in 0..15)
__device__ __forceinline__ int ahalf_idx(int r, int jl) {
    int lanep = (r & 7) * 4 + ((jl & 7) >> 1);
    int e = ((r >> 3) & 1) + 2 * ((jl >> 3) & 1);
    return (lanep * 4 + e) * 2 + (jl & 1);
}

__global__ __launch_bounds__(512, 1) void lstm_kernel(const float* __restrict__ x,
                                                      const float* __restrict__ Wfc,
                                                      const float* __restrict__ bfc,
                                                      float* __restrict__ out) {
    __shared__ __align__(16) unsigned AA[AAW];

    const int tid = threadIdx.x;
    const int w = tid >> 5;
    const int l = tid & 31;
    const int b0 = blockIdx.x * SLOTS;

    for (int i = tid; i < AAW; i += 512) AA[i] = 0u;
    __syncthreads();  // zeros visible before x(0) half-stores

    // stage x(0) into X ping
    if (tid < INPUT * SLOTS) {
        int s = tid & 15, k = tid >> 4;
        float v = x[(size_t)(b0 + s) * (TSTEPS * INPUT) + k];
        ((__half*)(AA + XO0))[(k >> 4) * 256 + ahalf_idx(s, k & 15)] = __float2half_rn(v);
    }

    // bias preload
    const int j0 = w * 8 + (l & 3) * 2;
    float bi0[4][2], bi1[4][2];
#pragma unroll
    for (int g = 0; g < 4; g++) {
        bi0[g][0] = g_B0[g * 128 + j0];
        bi0[g][1] = g_B0[g * 128 + j0 + 1];
        bi1[g][0] = g_B1[g * 128 + j0];
        bi1[g][1] = g_B1[g * 128 + j0 + 1];
    }

    float c0[4] = {0.f, 0.f, 0.f, 0.f};
    float c1[4] = {0.f, 0.f, 0.f, 0.f};

    const uint4* PAb = (const uint4*)g_PA + w * 64 + l;
    const uint4* PBb = (const uint4*)g_PB + w * 64 + l;
    __syncthreads();

    const int wbase = (w >> 1) * 128 + l * 4 + 2 * (w & 1);
    const int xs = tid & 15, xk = tid >> 4;  // x-staging coords (valid when tid<384)

#pragma unroll 1
    for (int t = 0; t < TSTEPS; t++) {
        const int pp = t & 1;
        const int h1c = pp ? H1O1 : H1O0;    // current h1 buffer (read)
        const int h1n = pp ? H1O0 : H1O1;    // next h1 buffer (written this step)
        const int xc = pp ? XO1 : XO0;
        const int xn = pp ? XO0 : XO1;

        // prefetch x(t+1) into a register (off the barrier path)
        float xv = 0.f;
        if (tid < INPUT * SLOTS) {
            int tn = (t + 1 < TSTEPS) ? t + 1 : t;
            xv = x[(size_t)(b0 + xs) * (TSTEPS * INPUT) + tn * INPUT + xk];
        }

        float d0[4][4], d1[4][4];
#pragma unroll
        for (int g = 0; g < 4; g++) {
            d0[g][0] = bi0[g][0]; d0[g][1] = bi0[g][1];
            d0[g][2] = bi0[g][0]; d0[g][3] = bi0[g][1];
            d1[g][0] = bi1[g][0]; d1[g][1] = bi1[g][1];
            d1[g][2] = bi1[g][0]; d1[g][3] = bi1[g][1];
        }

        // ---- fused GEMM_A: gates0 (ks0..9) + Whh1*h2 partial gates1 (ks10..17) ----
        gemm_A(PAb, AA + h1c, AA + xc, AA + H2O, l, d0, d1);

        // ---- epi0: h1 -> PONG region (no barrier needed; readers use ping) ----
        {
            unsigned hlo, hhi;
            cell4(d0, c0, hlo, hhi);
            AA[h1n + wbase] = hlo;
            AA[h1n + wbase + 1] = hhi;
        }
        if (tid < INPUT * SLOTS)
            ((__half*)(AA + xn))[(xk >> 4) * 256 + ahalf_idx(xs, xk & 15)] = __float2half_rn(xv);
        __syncthreads();  // publish h1(t) + x(t+1)

        // ---- GEMM_B: Wih1 * h1(t) into d1; epi1: h2 -> H2O ----
        gemm_B(PBb, AA + h1n, l, d1);
        {
            unsigned hlo, hhi;
            cell4(d1, c1, hlo, hhi);
            AA[H2O + wbase] = hlo;
            AA[H2O + wbase + 1] = hhi;
        }
        __syncthreads();  // publish h2(t) before next GEMM_A
    }

    // ---- final FC: out[b] = h2_last[b] . Wfc + bfc  (warp w -> batch row w) ----
    {
        int r = w;
        float s = 0.f;
#pragma unroll
        for (int jj = 0; jj < 4; jj++) {
            int j = l + jj * 32;
            float hv = __half2float(((__half*)(AA + H2O))[(j >> 4) * 256 + ahalf_idx(r, j & 15)]);
            s += hv * Wfc[j];
        }
#pragma unroll
        for (int o = 16; o > 0; o >>= 1) s += __shfl_down_sync(0xffffffffu, s, o);
        if (l == 0) out[b0 + r] = s + bfc[0];
    }
}

extern "C" void kernel_launch(void* const* d_in, const int* in_sizes, int n_in,
                              void* d_out, int out_size) {
    const float* x    = (const float*)d_in[0];
    const float* Wih0 = (const float*)d_in[1];
    const float* Whh0 = (const float*)d_in[2];
    const float* bih0 = (const float*)d_in[3];
    const float* bhh0 = (const float*)d_in[4];
    const float* Wih1 = (const float*)d_in[5];
    const float* Whh1 = (const float*)d_in[6];
    const float* bih1 = (const float*)d_in[7];
    const float* bhh1 = (const float*)d_in[8];
    const float* Wfc  = (const float*)d_in[9];
    const float* bfc  = (const float*)d_in[10];
    float* out = (float*)d_out;

    const int prep_total = NKA * 4096 + NKB * 4096 + 1024;
    prep_kernel<<<(prep_total + 255) / 256, 256>>>(Wih0, Whh0, bih0, bhh0, Wih1, Whh1, bih1, bhh1);
    lstm_kernel<<<BATCH / SLOTS, 512>>>(x, Wfc, bfc, out);
}

// round 17
// speedup vs baseline: 1.4160x; 1.0032x over previous
#include <cuda_runtime.h>
#include <cuda_fp16.h>

#define HID    128
#define INPUT  24
#define SLOTS  16
#define TSTEPS 128
#define BATCH  2048
#define NKA    18      // fused GEMM_A ksteps: 10 layer0 (128h+24x+8pad) + 8 Whh1
#define NKB    8       // GEMM_B ksteps: Wih1 (128)
#define WSA_KS 5       // GEMM_A ksteps resident in smem

// ---------------- packed fp16 weight fragments (device globals; no allocation) ----------------
// B-fragment order for mma.m16n8k16.row.col:
//   idx = (((ks*16 + w)*2 + q)*32 + l)*4 + r ;  g = q*2 + (r>>1), p = r&1
//   word = half2( W[n][k0], W[n][k0+1] ),  n = g*128 + w*8 + (l>>2),  k0 = ks*16 + (l&3)*2 + 8*p
__device__ unsigned g_PA[NKA * 4096];   // 288 KB: ks<10 layer0, ks>=10 Whh1
__device__ unsigned g_PB[NKB * 4096];   // 128 KB: Wih1
__device__ float g_B0[512];             // bih0 + bhh0, gate-major n index
__device__ float g_B1[512];

__global__ void prep_kernel(const float* __restrict__ Wih0, const float* __restrict__ Whh0,
                            const float* __restrict__ bih0, const float* __restrict__ bhh0,
                            const float* __restrict__ Wih1, const float* __restrict__ Whh1,
                            const float* __restrict__ bih1, const float* __restrict__ bhh1) {
    int idx = blockIdx.x * blockDim.x + threadIdx.x;
    const int NPA = NKA * 4096;
    const int NPB = NKB * 4096;
    if (idx < NPA) {
        int r = idx & 3, l = (idx >> 2) & 31, q = (idx >> 7) & 1, w = (idx >> 8) & 15, ks = idx >> 12;
        int g = q * 2 + (r >> 1), p = r & 1;
        int n = g * 128 + w * 8 + (l >> 2);
        float v0, v1;
        if (ks < 10) {
            int k0 = ks * 16 + (l & 3) * 2 + 8 * p;
            int k1 = k0 + 1;
            v0 = (k0 < HID) ? Whh0[n * HID + k0]
                            : ((k0 < HID + INPUT) ? Wih0[n * INPUT + (k0 - HID)] : 0.f);
            v1 = (k1 < HID) ? Whh0[n * HID + k1]
                            : ((k1 < HID + INPUT) ? Wih0[n * INPUT + (k1 - HID)] : 0.f);
        } else {
            int k0 = (ks - 10) * 16 + (l & 3) * 2 + 8 * p;
            v0 = Whh1[n * HID + k0];
            v1 = Whh1[n * HID + k0 + 1];
        }
        __half2 hv = __halves2half2(__float2half_rn(v0), __float2half_rn(v1));
        g_PA[idx] = *(unsigned*)&hv;
        return;
    }
    idx -= NPA;
    if (idx < NPB) {
        int r = idx & 3, l = (idx >> 2) & 31, q = (idx >> 7) & 1, w = (idx >> 8) & 15, ks = idx >> 12;
        int g = q * 2 + (r >> 1), p = r & 1;
        int n = g * 128 + w * 8 + (l >> 2);
        int k0 = ks * 16 + (l & 3) * 2 + 8 * p;
        __half2 hv = __halves2half2(__float2half_rn(Wih1[n * HID + k0]),
                                    __float2half_rn(Wih1[n * HID + k0 + 1]));
        g_PB[idx] = *(unsigned*)&hv;
        return;
    }
    idx -= NPB;
    if (idx < 1024) {
        int n = idx & 511;
        if (idx < 512) g_B0[n] = bih0[n] + bhh0[n];
        else           g_B1[n] = bih1[n] + bhh1[n];
    }
}

// ---------------- math helpers ----------------
__device__ __forceinline__ float sigf(float v) {
    return __fdividef(1.f, 1.f + __expf(-v));
}
__device__ __forceinline__ float tanhf_fast(float v) {
    return __fdividef(2.f, 1.f + __expf(-2.f * v)) - 1.f;
}

__device__ __forceinline__ void mma_f16(float d[4], const unsigned a[4], unsigned b0, unsigned b1) {
    asm volatile(
        "mma.sync.aligned.m16n8k16.row.col.f32.f16.f16.f32 "
        "{%0,%1,%2,%3}, {%4,%5,%6,%7}, {%8,%9}, {%0,%1,%2,%3};"
        : "+f"(d[0]), "+f"(d[1]), "+f"(d[2]), "+f"(d[3])
        : "r"(a[0]), "r"(a[1]), "r"(a[2]), "r"(a[3]), "r"(b0), "r"(b1));
}

// ---- dynamic smem layout (unsigned units) ----
//   [0, 20480)        WS_A: smem-resident PA ksteps 0..4   (80 KB)
//   [20480, 53248)    WS_B: smem-resident PB ksteps 0..7   (128 KB)
//   [53248, 56832)    AA activation buffer                 (14.3 KB)
#define WSB_U  20480
#define AAO    53248
#define SMEMW  56832     // 227328 bytes total

// AA-relative word offsets
#define H1O0  0
#define H1O1  1024
#define XO0   2048
#define XO1   2304
#define H2O   2560

// Fused GEMM_A: 18 ksteps, fully unrolled; ks<10 -> d0, ks>=10 -> d1.
// B source: smem ring for ks<WSA_KS, global beyond (selected at compile time).
#define SRC_A(KS) (((KS) < WSA_KS) ? (wsa + (KS) * 1024) : (pa + (KS) * 1024))
__device__ __forceinline__ void gemm_A(const uint4* __restrict__ pa,
                                       const uint4* __restrict__ wsa,
                                       const unsigned* __restrict__ h1c,
                                       const unsigned* __restrict__ xc,
                                       const unsigned* __restrict__ h2b,
                                       int l, float d0[4][4], float d1[4][4]) {
    uint4 b[4][2];
#pragma unroll
    for (int p = 0; p < 4; p++) {
        const uint4* s = SRC_A(p);
        b[p][0] = s[0];
        b[p][1] = s[32];
    }
    unsigned a[2][4];
    *(uint4*)a[0] = *(const uint4*)(h1c + l * 4);
#pragma unroll
    for (int ks = 0; ks < NKA; ks++) {
        if (ks + 1 < NKA) {
            const unsigned* nb = (ks + 1 < 8) ? h1c + (ks + 1) * 128
                               : (ks + 1 < 10) ? xc + (ks + 1 - 8) * 128
                                               : h2b + (ks + 1 - 10) * 128;
            *(uint4*)a[(ks + 1) & 1] = *(const uint4*)(nb + l * 4);
        }
        const unsigned* ac = a[ks & 1];
        float(*d)[4] = (ks < 10) ? d0 : d1;
        const int slot = ks & 3;
        mma_f16(d[0], ac, b[slot][0].x, b[slot][0].y);
        mma_f16(d[1], ac, b[slot][0].z, b[slot][0].w);
        mma_f16(d[2], ac, b[slot][1].x, b[slot][1].y);
        mma_f16(d[3], ac, b[slot][1].z, b[slot][1].w);
        if (ks + 4 < NKA) {
            const uint4* s = SRC_A(ks + 4);
            b[slot][0] = s[0];
            b[slot][1] = s[32];
        }
    }
}

// GEMM_B: 8 ksteps of Wih1 x h1(t) into d1 — B entirely from smem.
__device__ __forceinline__ void gemm_B(const uint4* __restrict__ wsb,
                                       const unsigned* __restrict__ h1n,
                                       int l, float d1[4][4]) {
    uint4 b[4][2];
#pragma unroll
    for (int p = 0; p < 4; p++) {
        b[p][0] = wsb[p * 1024];
        b[p][1] = wsb[p * 1024 + 32];
    }
    unsigned a[2][4];
    *(uint4*)a[0] = *(const uint4*)(h1n + l * 4);
#pragma unroll
    for (int ks = 0; ks < NKB; ks++) {
        if (ks + 1 < NKB)
            *(uint4*)a[(ks + 1) & 1] = *(const uint4*)(h1n + (ks + 1) * 128 + l * 4);
        const unsigned* ac = a[ks & 1];
        const int slot = ks & 3;
        mma_f16(d1[0], ac, b[slot][0].x, b[slot][0].y);
        mma_f16(d1[1], ac, b[slot][0].z, b[slot][0].w);
        mma_f16(d1[2], ac, b[slot][1].x, b[slot][1].y);
        mma_f16(d1[3], ac, b[slot][1].z, b[slot][1].w);
        if (ks + 4 < NKB) {
            b[slot][0] = wsb[(ks + 4) * 1024];
            b[slot][1] = wsb[(ks + 4) * 1024 + 32];
        }
    }
}

// cell update for this lane's 4 cells; returns two packed half2 words (rows r0, r0+8).
__device__ __forceinline__ void cell4(const float d[4][4], float c[4],
                                      unsigned& hlo, unsigned& hhi) {
    float h[4];
#pragma unroll
    for (int i = 0; i < 4; i++) {
        float iv = sigf(d[0][i]);
        float fv = sigf(d[1][i]);
        float gv = tanhf_fast(d[2][i]);
        float ov = sigf(d[3][i]);
        c[i] = fv * c[i] + iv * gv;
        h[i] = ov * tanhf_fast(c[i]);
    }
    __half2 a = __halves2half2(__float2half_rn(h[0]), __float2half_rn(h[1]));
    __half2 b = __halves2half2(__float2half_rn(h[2]), __float2half_rn(h[3]));
    hlo = *(unsigned*)&a;
    hhi = *(unsigned*)&b;
}

// half index (within one kstep) for A-frag value (row r, col jl in 0..15)
__device__ __forceinline__ int ahalf_idx(int r, int jl) {
    int lanep = (r & 7) * 4 + ((jl & 7) >> 1);
    int e = ((r >> 3) & 1) + 2 * ((jl >> 3) & 1);
    return (lanep * 4 + e) * 2 + (jl & 1);
}

__global__ __launch_bounds__(512, 1) void lstm_kernel(const float* __restrict__ x,
                                                      const float* __restrict__ Wfc,
                                                      const float* __restrict__ bfc,
                                                      float* __restrict__ out) {
    extern __shared__ __align__(16) unsigned smu[];
    unsigned* AA = smu + AAO;

    const int tid = threadIdx.x;
    const int w = tid >> 5;
    const int l = tid & 31;
    const int b0 = blockIdx.x * SLOTS;

    // ---- load weight cache: PA ks0..4 + all of PB into smem (once) ----
    {
        uint4* ws = (uint4*)smu;
        const uint4* gpa = (const uint4*)g_PA;
        const uint4* gpb = (const uint4*)g_PB;
        for (int i = tid; i < WSA_KS * 1024; i += 512) ws[i] = gpa[i];
        for (int i = tid; i < NKB * 1024; i += 512) ws[WSA_KS * 1024 + i] = gpb[i];
    }
    for (int i = tid; i < SMEMW - AAO; i += 512) AA[i] = 0u;
    __syncthreads();  // cache + zeros visible

    // stage x(0) into X ping
    if (tid < INPUT * SLOTS) {
        int s = tid & 15, k = tid >> 4;
        float v = x[(size_t)(b0 + s) * (TSTEPS * INPUT) + k];
        ((__half*)(AA + XO0))[(k >> 4) * 256 + ahalf_idx(s, k & 15)] = __float2half_rn(v);
    }

    // bias preload
    const int j0 = w * 8 + (l & 3) * 2;
    float bi0[4][2], bi1[4][2];
#pragma unroll
    for (int g = 0; g < 4; g++) {
        bi0[g][0] = g_B0[g * 128 + j0];
        bi0[g][1] = g_B0[g * 128 + j0 + 1];
        bi1[g][0] = g_B1[g * 128 + j0];
        bi1[g][1] = g_B1[g * 128 + j0 + 1];
    }

    float c0[4] = {0.f, 0.f, 0.f, 0.f};
    float c1[4] = {0.f, 0.f, 0.f, 0.f};

    const uint4* PAb = (const uint4*)g_PA + w * 64 + l;
    const uint4* WSAb = (const uint4*)smu + w * 64 + l;
    const uint4* WSBb = (const uint4*)smu + WSB_U / 4 + w * 64 + l;
    __syncthreads();

    const int wbase = (w >> 1) * 128 + l * 4 + 2 * (w & 1);
    const int xs = tid & 15, xk = tid >> 4;  // x-staging coords (valid when tid<384)

#pragma unroll 1
    for (int t = 0; t < TSTEPS; t++) {
        const int pp = t & 1;
        const int h1c = pp ? H1O1 : H1O0;
        const int h1n = pp ? H1O0 : H1O1;
        const int xc = pp ? XO1 : XO0;
        const int xn = pp ? XO0 : XO1;

        // prefetch x(t+1) into a register (off the barrier path)
        float xv = 0.f;
        if (tid < INPUT * SLOTS) {
            int tn = (t + 1 < TSTEPS) ? t + 1 : t;
            xv = x[(size_t)(b0 + xs) * (TSTEPS * INPUT) + tn * INPUT + xk];
        }

        float d0[4][4], d1[4][4];
#pragma unroll
        for (int g = 0; g < 4; g++) {
            d0[g][0] = bi0[g][0]; d0[g][1] = bi0[g][1];
            d0[g][2] = bi0[g][0]; d0[g][3] = bi0[g][1];
            d1[g][0] = bi1[g][0]; d1[g][1] = bi1[g][1];
            d1[g][2] = bi1[g][0]; d1[g][3] = bi1[g][1];
        }

        // ---- fused GEMM_A: gates0 (ks0..9) + Whh1*h2 partial gates1 (ks10..17) ----
        gemm_A(PAb, WSAb, AA + h1c, AA + xc, AA + H2O, l, d0, d1);

        // ---- epi0: h1 -> PONG region (no barrier needed; readers use ping) ----
        {
            unsigned hlo, hhi;
            cell4(d0, c0, hlo, hhi);
            AA[h1n + wbase] = hlo;
            AA[h1n + wbase + 1] = hhi;
        }
        if (tid < INPUT * SLOTS)
            ((__half*)(AA + xn))[(xk >> 4) * 256 + ahalf_idx(xs, xk & 15)] = __float2half_rn(xv);
        __syncthreads();  // publish h1(t) + x(t+1)

        // ---- GEMM_B: Wih1 * h1(t) into d1 (B from smem); epi1: h2 -> H2O ----
        gemm_B(WSBb, AA + h1n, l, d1);
        {
            unsigned hlo, hhi;
            cell4(d1, c1, hlo, hhi);
            AA[H2O + wbase] = hlo;
            AA[H2O + wbase + 1] = hhi;
        }
        __syncthreads();  // publish h2(t) before next GEMM_A
    }

    // ---- final FC: out[b] = h2_last[b] . Wfc + bfc  (warp w -> batch row w) ----
    {
        int r = w;
        float s = 0.f;
#pragma unroll
        for (int jj = 0; jj < 4; jj++) {
            int j = l + jj * 32;
            float hv = __half2float(((__half*)(AA + H2O))[(j >> 4) * 256 + ahalf_idx(r, j & 15)]);
            s += hv * Wfc[j];
        }
#pragma unroll
        for (int o = 16; o > 0; o >>= 1) s += __shfl_down_sync(0xffffffffu, s, o);
        if (l == 0) out[b0 + r] = s + bfc[0];
    }
}

extern "C" void kernel_launch(void* const* d_in, const int* in_sizes, int n_in,
                              void* d_out, int out_size) {
    const float* x    = (const float*)d_in[0];
    const float* Wih0 = (const float*)d_in[1];
    const float* Whh0 = (const float*)d_in[2];
    const float* bih0 = (const float*)d_in[3];
    const float* bhh0 = (const float*)d_in[4];
    const float* Wih1 = (const float*)d_in[5];
    const float* Whh1 = (const float*)d_in[6];
    const float* bih1 = (const float*)d_in[7];
    const float* bhh1 = (const float*)d_in[8];
    const float* Wfc  = (const float*)d_in[9];
    const float* bfc  = (const float*)d_in[10];
    float* out = (float*)d_out;

    const int smem_bytes = SMEMW * 4;  // 227328
    cudaFuncSetAttribute(lstm_kernel, cudaFuncAttributeMaxDynamicSharedMemorySize, smem_bytes);

    const int prep_total = NKA * 4096 + NKB * 4096 + 1024;
    prep_kernel<<<(prep_total + 255) / 256, 256>>>(Wih0, Whh0, bih0, bhh0, Wih1, Whh1, bih1, bhh1);
    lstm_kernel<<<BATCH / SLOTS, 512, smem_bytes>>>(x, Wfc, bfc, out);
}